// round 5
// baseline (speedup 1.0000x reference)
#include <cuda_runtime.h>

// HamiltonianEvolution: out = q_left_n ⊗ (gate*x) ⊗ conj(q_right_n).
// FFT/IFFT pair is an identity (gate constant along the FFT axis) -> per-
// channel 4x4 linear map. This version: one thread owns ONE channel j, so its
// 4x4 matrix M lives in 16 registers (no smem, no syncthreads). Threads with
// consecutive j give perfectly coalesced LDG.32/STG.32 streams. 4 rows per
// iteration are front-batched (MLP=16 scalar loads in flight per thread).

#define QD 256            // quat_dim (= threads per block)
#define DM 1024           // d_model (floats per row)
#define ROWS_PER_BLOCK 16
#define ROWS_PER_ITER 4

__global__ __launch_bounds__(256, 5)
void fused_kernel(const float* __restrict__ q_left,
                  const float* __restrict__ q_right,
                  const float* __restrict__ gate,
                  const float* __restrict__ x,
                  float* __restrict__ out,
                  int nrows) {
    const int j = threadIdx.x;   // channel 0..255

    // ---- per-thread composite matrix M = gate * L(q_left_n) @ R(conj(q_right_n)) ----
    float m[4][4];
    {
        float lw = q_left[0 * QD + j], lx = q_left[1 * QD + j];
        float ly = q_left[2 * QD + j], lz = q_left[3 * QD + j];
        float rw = q_right[0 * QD + j], rx = q_right[1 * QD + j];
        float ry = q_right[2 * QD + j], rz = q_right[3 * QD + j];

        float ln = rsqrtf(lw * lw + lx * lx + ly * ly + lz * lz + 1e-8f);
        lw *= ln; lx *= ln; ly *= ln; lz *= ln;
        float rn = rsqrtf(rw * rw + rx * rx + ry * ry + rz * rz + 1e-8f);
        rw = rw * rn; rx = -rx * rn; ry = -ry * rn; rz = -rz * rn;

        const float g = gate[j];

        // R: p -> p ⊗ rc (rc = conjugated normalized q_right)
        const float R[4][4] = {
            { rw, -rx, -ry, -rz},
            { rx,  rw,  rz, -ry},
            { ry, -rz,  rw,  rx},
            { rz,  ry, -rx,  rw}
        };
        // L: p -> l ⊗ p (l = normalized q_left)
        const float L[4][4] = {
            { lw, -lx, -ly, -lz},
            { lx,  lw, -lz,  ly},
            { ly,  lz,  lw, -lx},
            { lz, -ly,  lx,  lw}
        };

        #pragma unroll
        for (int r = 0; r < 4; r++) {
            #pragma unroll
            for (int c = 0; c < 4; c++) {
                float acc = 0.0f;
                #pragma unroll
                for (int k = 0; k < 4; k++) acc += L[r][k] * R[k][c];
                m[r][c] = g * acc;
            }
        }
    }

    const int base = blockIdx.x * ROWS_PER_BLOCK;

    #pragma unroll
    for (int it = 0; it < ROWS_PER_BLOCK / ROWS_PER_ITER; it++) {
        const int r0 = base + it * ROWS_PER_ITER;

        // front-batched loads: 16 independent LDG.32 in flight
        float in[ROWS_PER_ITER][4];
        #pragma unroll
        for (int rr = 0; rr < ROWS_PER_ITER; rr++) {
            const int row = r0 + rr;
            if (row < nrows) {
                const float* xr = x + (size_t)row * DM + j;
                in[rr][0] = xr[0 * QD];
                in[rr][1] = xr[1 * QD];
                in[rr][2] = xr[2 * QD];
                in[rr][3] = xr[3 * QD];
            }
        }

        #pragma unroll
        for (int rr = 0; rr < ROWS_PER_ITER; rr++) {
            const int row = r0 + rr;
            if (row < nrows) {
                float ow = fmaf(m[0][0], in[rr][0], fmaf(m[0][1], in[rr][1],
                           fmaf(m[0][2], in[rr][2], m[0][3] * in[rr][3])));
                float ox = fmaf(m[1][0], in[rr][0], fmaf(m[1][1], in[rr][1],
                           fmaf(m[1][2], in[rr][2], m[1][3] * in[rr][3])));
                float oy = fmaf(m[2][0], in[rr][0], fmaf(m[2][1], in[rr][1],
                           fmaf(m[2][2], in[rr][2], m[2][3] * in[rr][3])));
                float oz = fmaf(m[3][0], in[rr][0], fmaf(m[3][1], in[rr][1],
                           fmaf(m[3][2], in[rr][2], m[3][3] * in[rr][3])));

                float* orow = out + (size_t)row * DM + j;
                orow[0 * QD] = ow;
                orow[1 * QD] = ox;
                orow[2 * QD] = oy;
                orow[3 * QD] = oz;
            }
        }
    }
}

extern "C" void kernel_launch(void* const* d_in, const int* in_sizes, int n_in,
                              void* d_out, int out_size) {
    const float* x    = (const float*)d_in[0];   // (B, T, 1024)
    const float* q_l  = (const float*)d_in[1];   // (4, 256)
    const float* q_r  = (const float*)d_in[2];   // (4, 256)
    const float* gate = (const float*)d_in[3];   // (1,1,1,256)

    const int nrows = in_sizes[0] / DM;          // B*T = 16384
    const int grid = (nrows + ROWS_PER_BLOCK - 1) / ROWS_PER_BLOCK;  // 1024

    fused_kernel<<<grid, 256>>>(q_l, q_r, gate, x, (float*)d_out, nrows);
}